// round 14
// baseline (speedup 1.0000x reference)
#include <cuda_runtime.h>
#include <math.h>

#define B_IMG   64
#define NPIX    1024
#define NSTATE  (B_IMG*8*NPIX)      // 524288
#define N_STEPS 24

typedef unsigned long long ull;
typedef unsigned int uint;

__device__ __forceinline__ ull pack2(float lo, float hi) {
  ull r; asm("mov.b64 %0, {%1, %2};" : "=l"(r) : "f"(lo), "f"(hi)); return r;
}
__device__ __forceinline__ float2 unpk(ull v) {
  float2 f; asm("mov.b64 {%0, %1}, %2;" : "=f"(f.x), "=f"(f.y) : "l"(v)); return f;
}
#define FMA2(d,a,b) asm("fma.rn.f32x2 %0, %1, %2, %0;" : "+l"(d) : "l"(a), "l"(b))

__device__ __forceinline__ uint f2tf32(float x) {
  uint r; asm("cvt.rna.tf32.f32 %0, %1;" : "=r"(r) : "f"(x)); return r;
}
__device__ __forceinline__ void mma_tf32(float* d, const uint* a, uint b0, uint b1) {
  asm volatile("mma.sync.aligned.m16n8k8.row.col.f32.tf32.tf32.f32 "
    "{%0,%1,%2,%3}, {%4,%5,%6,%7}, {%8,%9}, {%0,%1,%2,%3};"
    : "+f"(d[0]), "+f"(d[1]), "+f"(d[2]), "+f"(d[3])
    : "r"(a[0]), "r"(a[1]), "r"(a[2]), "r"(a[3]), "r"(b0), "r"(b1));
}
__device__ __forceinline__ void cpa16(void* smem_dst, const void* gsrc) {
  unsigned s = (unsigned)__cvta_generic_to_shared(smem_dst);
  asm volatile("cp.async.ca.shared.global [%0], [%1], 16;" :: "r"(s), "l"(gsrc));
}
#define CP_COMMIT() asm volatile("cp.async.commit_group;")
#define CP_WAIT0()  asm volatile("cp.async.wait_group 0;")

// ---------------- device state ----------------
__device__ float g_y[NSTATE];
__device__ float g_y5[NSTATE];
__device__ float g_k[7][NSTATE];
__device__ float g_t, g_dt;
__device__ float g_partial[2048];
__device__ int   g_accept;

// packed weights
__device__ uint4 g_w2q[18432];  // [cc8][tap9][och64][cq4]: (hi_cq, lo_cq, hi_cq4, lo_cq4)
__device__ ull g_w1s[256];      // [c8][o2_32]
__device__ ull g_w1t[32], g_b1p[32];
__device__ ull g_w3s[256];      // [ci64][o2_4]
__device__ ull g_w3t[4], g_b3p[4];
__device__ float g_w0f[576];    // conv2 t-channel [och64][tap9]
__device__ float g_b2f[64];

__constant__ float c_toff[7] = {0.f, 0.2f, 0.3f, 0.8f, (float)(8.0/9.0), 1.f, 1.f};
__constant__ float c_coef[7][6] = {
  {0,0,0,0,0,0},
  {0.2f,0,0,0,0,0},
  {(float)(3.0/40.0),(float)(9.0/40.0),0,0,0,0},
  {(float)(44.0/45.0),(float)(-56.0/15.0),(float)(32.0/9.0),0,0,0},
  {(float)(19372.0/6561.0),(float)(-25360.0/2187.0),(float)(64448.0/6561.0),(float)(-212.0/729.0),0,0},
  {(float)(9017.0/3168.0),(float)(-355.0/33.0),(float)(46732.0/5247.0),(float)(49.0/176.0),(float)(-5103.0/18656.0),0},
  {(float)(35.0/384.0),0.f,(float)(500.0/1113.0),(float)(125.0/192.0),(float)(-2187.0/6784.0),(float)(11.0/84.0)}
};
#define B1f ((float)(35.0/384.0))
#define B3f ((float)(500.0/1113.0))
#define B4f ((float)(125.0/192.0))
#define B5f ((float)(-2187.0/6784.0))
#define B6f ((float)(11.0/84.0))
#define E1f ((float)(71.0/57600.0))
#define E3f ((float)(-71.0/16695.0))
#define E4f ((float)(71.0/1920.0))
#define E5f ((float)(-17253.0/339200.0))
#define E6f ((float)(22.0/525.0))
#define E7f ((float)(-1.0/40.0))

// ---------------- init ----------------
__global__ void init_kernel(const float* __restrict__ x) {
  int i = blockIdx.x * 256 + threadIdx.x;
  if (i == 0) { g_t = 0.f; g_dt = 0.1f; g_accept = 0; }
  if (i < NSTATE) {
    int c = i & 7, p = (i >> 3) & 1023, b = i >> 13;
    g_y[i] = (c < 3) ? x[b*3*NPIX + c*NPIX + p] : 0.f;
  }
}

// ---------------- weight prep (verbatim R13) ----------------
__global__ void prep_kernel(const float* __restrict__ w1, const float* __restrict__ b1,
                            const float* __restrict__ w2, const float* __restrict__ b2,
                            const float* __restrict__ w3, const float* __restrict__ b3) {
  int i = blockIdx.x * 256 + threadIdx.x;
  if (i < 18432) {
    int cq  = i & 3;
    int och = (i >> 2) & 63;
    int t   = (i >> 8) % 9;
    int cc  = i / 2304;
    float wa = w2[och*585 + (cc*8 + cq + 1)*9 + t];
    float wb = w2[och*585 + (cc*8 + cq + 5)*9 + t];
    uint hia = f2tf32(wa);
    uint loa = f2tf32(wa - __uint_as_float(hia));
    uint hib = f2tf32(wb);
    uint lob = f2tf32(wb - __uint_as_float(hib));
    g_w2q[i] = make_uint4(hia, loa, hib, lob);
  }
  if (i < 256) {
    int c = i >> 5, o2 = i & 31;
    g_w1s[i] = pack2(w1[(2*o2)*9 + 1 + c], w1[(2*o2+1)*9 + 1 + c]);
  }
  if (i < 32) {
    g_w1t[i] = pack2(w1[(2*i)*9], w1[(2*i+1)*9]);
    g_b1p[i] = pack2(b1[2*i], b1[2*i+1]);
  }
  if (i < 256) {
    int c = i >> 2, o2 = i & 3;
    g_w3s[i] = pack2(w3[(2*o2)*65 + 1 + c], w3[(2*o2+1)*65 + 1 + c]);
  }
  if (i < 4) {
    g_w3t[i] = pack2(w3[(2*i)*65], w3[(2*i+1)*65]);
    g_b3p[i] = pack2(b3[2*i], b3[2*i+1]);
  }
  if (i < 576) {
    int och = i / 9, t = i % 9;
    g_w0f[i] = w2[och*585 + t];
  }
  if (i < 64) g_b2f[i] = b2[i];
}

// ---------------- fused stage kernel: warp-specialized, 384 threads ----------------
// grid (64 img, 8 tiles); block 384 thr = 12 warps.
// Warps 0-7 = CONSUMERS: warp w -> row-group cw = w>>1, och-half oh = w&1
//   (acc[2][4][4] = 32 regs; 4 consumer warps per SMSP across 2 CTAs).
// Warps 8-11 = PRODUCERS (conv1 + weight cp.async) — code verbatim R13.
// 9 phases: producers build chunk ph while consumers mma chunk ph-1.
// Float arithmetic verbatim from R13 (same accumulation order per output).
#define HP 210            // h1q pitch (uint4)
#define HB 840            // h1q buffer stride (uint4) = 4*HP
#define SM_YTS   0        // float yts[204][8]                 6528 B
#define SM_H1    6528     // uint4 h1q[2][4][HP]              26880 B
#define SM_WB    33408    // uint4 wb[2][2304]                73728 B  (h2s overlays wb[0])
#define SM_W1    107136   // ull w1s[256]                      2048 B
#define SM_B1    109184   // ull bias1[32]                      256 B
#define SM_W3    109440   // ull w3s[256]                      2048 B
#define SM_W0    111488   // float w0f[576]                    2304 B
#define SM_B2    113792   // float b2f[64]                      256 B
#define SMEM_BYTES 114048

__global__ __launch_bounds__(384, 2) void fused_kernel(int stage) {
  extern __shared__ char smraw[];
  float* yts  = (float*)(smraw + SM_YTS);
  uint4* h1q  = (uint4*)(smraw + SM_H1);
  uint4* wbu  = (uint4*)(smraw + SM_WB);
  float* h2s  = (float*)(smraw + SM_WB);       // overlay on wb[0] after K loop
  ull*   w1s  = (ull*)  (smraw + SM_W1);
  ull*   bias1= (ull*)  (smraw + SM_B1);
  ull*   w3s  = (ull*)  (smraw + SM_W3);
  float* w0f  = (float*)(smraw + SM_W0);
  float* b2f  = (float*)(smraw + SM_B2);

  int tid  = threadIdx.x;
  int b    = blockIdx.x;
  int tile = blockIdx.y;
  int r0   = tile * 4;

  int warp = tid >> 5, lane = tid & 31;
  int g   = lane >> 2;
  int cq  = lane & 3;
  bool is_cons = (warp < 8);
  int cw   = warp >> 1;     // consumer row group (0..3)
  int oh   = warp & 1;      // consumer och half (0..1)
  int ptid = tid - 256;     // producer thread id (0..127)

  float tcur = g_t;
  float dtc  = fminf(g_dt, 1.f - tcur);
  float teval = tcur + c_toff[stage] * dtc;
  ull tev2 = pack2(teval, teval);

  // small weights -> smem (all threads)
  for (int i = tid; i < 256; i += 384) w1s[i] = g_w1s[i];
  for (int i = tid; i < 256; i += 384) w3s[i] = g_w3s[i];
  for (int i = tid; i < 576; i += 384) w0f[i] = g_w0f[i];
  if (tid < 64) b2f[tid] = g_b2f[tid];
  if (tid < 32) { ull bb = g_b1p[tid]; FMA2(bb, tev2, g_w1t[tid]); bias1[tid] = bb; }

  // ---- phase A: stage-combined state into yts (haloed 6x34) — verbatim float code ----
  for (int p = tid; p < 204; p += 384) {
    int prow = p / 34, pcol = p - prow*34;
    int gr = r0 - 1 + prow, gc = pcol - 1;
    float4 o0 = make_float4(0.f,0.f,0.f,0.f), o1 = o0;
    if (gr >= 0 && gr < 32 && gc >= 0 && gc < 32) {
      int idx = b*1024 + gr*32 + gc;
      const float4* yp = (const float4*)g_y;
      o0 = yp[idx*2]; o1 = yp[idx*2+1];
      for (int j = 0; j < stage; j++) {
        float cf = c_coef[stage][j];
        if (cf != 0.f) {
          float a = dtc * cf;
          const float4* kj = (const float4*)g_k[j];
          float4 k0 = kj[idx*2], k1 = kj[idx*2+1];
          o0.x+=a*k0.x; o0.y+=a*k0.y; o0.z+=a*k0.z; o0.w+=a*k0.w;
          o1.x+=a*k1.x; o1.y+=a*k1.y; o1.z+=a*k1.z; o1.w+=a*k1.w;
        }
      }
    }
    float4* dst = (float4*)(yts + p*8);
    dst[0] = o0; dst[1] = o1;
  }
  __syncthreads();   // yts ready for producers

  // consumer accumulators: acc[mtl2][nt4][4]
  float acc[2][4][4];
  #pragma unroll
  for (int mtl = 0; mtl < 2; mtl++)
    #pragma unroll
    for (int nt = 0; nt < 4; nt++)
      #pragma unroll
      for (int q = 0; q < 4; q++) acc[mtl][nt][q] = 0.f;

  const int abase = g*4 + cq + oh*2*64;     // A: + t*256 + mtl*64 (+32 for row g+8)
  const int hbase = cq*HP + cw*34 + g;      // B: + kh*34 + kw + nt*8 (+ buf*HB)

  // ---- 9 phases: producers(chunk ph) || consumers(chunk ph-1) ----
  #pragma unroll 1
  for (int ph = 0; ph < 9; ph++) {
    if (!is_cons) {
      // PRODUCERS: verbatim R13
      if (ph < 8) {
        const int cc = ph;
        const int buf = cc & 1;
        {
          const uint4* src = g_w2q + cc*2304;
          uint4* dst = wbu + buf*2304;
          for (int i = ptid; i < 2304; i += 128) cpa16(dst + i, src + i);
          CP_COMMIT();
        }
        #pragma unroll 1
        for (int p = ptid; p < 204; p += 128) {
          int prow = p / 34, pcol = p - prow*34;
          int gr = r0 - 1 + prow, gc = pcol - 1;
          float o[8];
          if (gr >= 0 && gr < 32 && gc >= 0 && gc < 32) {
            const float4* yv = (const float4*)(yts + p*8);
            float4 a4 = yv[0], b4 = yv[1];
            float yf[8] = {a4.x, a4.y, a4.z, a4.w, b4.x, b4.y, b4.z, b4.w};
            ull yy[8];
            #pragma unroll
            for (int c8 = 0; c8 < 8; c8++) yy[c8] = pack2(yf[c8], yf[c8]);
            #pragma unroll
            for (int q = 0; q < 4; q++) {
              ull aq = bias1[cc*4 + q];
              #pragma unroll
              for (int c8 = 0; c8 < 8; c8++) FMA2(aq, yy[c8], w1s[c8*32 + cc*4 + q]);
              float2 f = unpk(aq);
              o[2*q]   = fmaxf(f.x, 0.f);
              o[2*q+1] = fmaxf(f.y, 0.f);
            }
          } else {
            #pragma unroll
            for (int q = 0; q < 8; q++) o[q] = 0.f;
          }
          #pragma unroll
          for (int ci = 0; ci < 4; ci++) {
            float v0 = o[ci], v1 = o[ci+4];
            uint h0 = __float_as_uint(v0) & 0xffffe000u;
            uint h1 = __float_as_uint(v1) & 0xffffe000u;
            float l0 = v0 - __uint_as_float(h0);
            float l1 = v1 - __uint_as_float(h1);
            h1q[buf*HB + ci*HP + p] = make_uint4(h0, __float_as_uint(l0), h1, __float_as_uint(l1));
          }
        }
        CP_WAIT0();
      }
    } else {
      // CONSUMERS: mma chunk ph-1, och-half oh only
      if (ph >= 1) {
        const int cc = ph - 1;
        const int buf = cc & 1;
        const uint4* wc = wbu + buf*2304;
        #pragma unroll
        for (int t = 0; t < 9; t++) {
          const int kh = t / 3, kw = t - kh*3;
          uint4 Bv[4];
          #pragma unroll
          for (int nt = 0; nt < 4; nt++)
            Bv[nt] = h1q[buf*HB + hbase + kh*34 + kw + nt*8];
          #pragma unroll
          for (int mtl = 0; mtl < 2; mtl++) {
            uint4 A0 = wc[abase + t*256 + mtl*64];
            uint4 A1 = wc[abase + t*256 + mtl*64 + 32];
            uint ahi[4] = {A0.x, A1.x, A0.z, A1.z};
            uint alo[4] = {A0.y, A1.y, A0.w, A1.w};
            #pragma unroll
            for (int nt = 0; nt < 4; nt++) {
              mma_tf32(acc[mtl][nt], ahi, Bv[nt].x, Bv[nt].z);
              mma_tf32(acc[mtl][nt], ahi, Bv[nt].y, Bv[nt].w);
              mma_tf32(acc[mtl][nt], alo, Bv[nt].x, Bv[nt].z);
            }
          }
        }
      }
    }
    __syncthreads();
  }

  // ---- epilogue (consumers): t-channel + bias + relu -> h2s[row4][och64][33] ----
  // Float expressions verbatim R13.
  if (is_cons) {
    int gr = r0 + cw;
    bool r0ok = (gr != 0);
    bool r2ok = (gr != 31);
    #pragma unroll
    for (int mtl = 0; mtl < 2; mtl++) {
      #pragma unroll
      for (int rh = 0; rh < 2; rh++) {
        int och = (oh*2 + mtl)*16 + g + rh*8;
        const float* w0 = w0f + och*9;
        float cs0 = w0[3], cs1 = w0[4], cs2 = w0[5];
        if (r0ok) { cs0 += w0[0]; cs1 += w0[1]; cs2 += w0[2]; }
        if (r2ok) { cs0 += w0[6]; cs1 += w0[7]; cs2 += w0[8]; }
        float ball = cs0 + cs1 + cs2;
        float bias = b2f[och];
        float* hrow = h2s + (cw*64 + och)*33;
        #pragma unroll
        for (int nt = 0; nt < 4; nt++) {
          #pragma unroll
          for (int cb = 0; cb < 2; cb++) {
            int colx = nt*8 + 2*cq + cb;
            float s = ball;
            if (colx == 0)  s -= cs0;
            if (colx == 31) s -= cs2;
            float v = acc[mtl][nt][rh*2 + cb] + teval*s + bias;
            hrow[colx] = fmaxf(v, 0.f);
          }
        }
      }
    }
  }
  __syncthreads();

  // ---- conv3 (65->8 1x1): 256 of 384 threads, 2 threads/px — verbatim R13 ----
  if (tid < 256) {
    int px   = tid >> 1;
    int half = tid & 1;
    int row = px >> 5, col = px & 31;
    int o2a = half*2, o2b = half*2 + 1;
    ull k0 = g_b3p[o2a]; FMA2(k0, tev2, g_w3t[o2a]);
    ull k1 = g_b3p[o2b]; FMA2(k1, tev2, g_w3t[o2b]);
    const float* hcol = h2s + (row*64)*33 + col;
    #pragma unroll 8
    for (int c = 0; c < 64; c++) {
      float h = hcol[c*33];
      ull hh = pack2(h, h);
      FMA2(k0, hh, w3s[c*4 + o2a]);
      FMA2(k1, hh, w3s[c*4 + o2b]);
    }
    float2 f0 = unpk(k0), f1 = unpk(k1);
    int idx = b*1024 + (r0 + row)*32 + col;
    ((float4*)g_k[stage])[idx*2 + half] = make_float4(f0.x, f0.y, f1.x, f1.y);
  }
}

// ---------------- y5 + error partials (verbatim R13) ----------------
__global__ __launch_bounds__(256) void err_kernel() {
  __shared__ float red[256];
  int tid = threadIdx.x;
  int e = blockIdx.x * 256 + tid;
  float dtc = fminf(g_dt, 1.f - g_t);
  float k0 = g_k[0][e], k2 = g_k[2][e], k3 = g_k[3][e];
  float k4 = g_k[4][e], k5 = g_k[5][e], k6 = g_k[6][e];
  float yv = g_y[e];
  float y5 = yv + dtc*(B1f*k0 + B3f*k2 + B4f*k3 + B5f*k4 + B6f*k5);
  g_y5[e] = y5;
  float err = dtc*(E1f*k0 + E3f*k2 + E4f*k3 + E5f*k4 + E6f*k5 + E7f*k6);
  float tol = 1e-3f + 1e-3f * fmaxf(fabsf(yv), fabsf(y5));
  float r = err / tol;
  red[tid] = r * r;
  __syncthreads();
  for (int s = 128; s > 0; s >>= 1) { if (tid < s) red[tid] += red[tid+s]; __syncthreads(); }
  if (tid == 0) g_partial[blockIdx.x] = red[0];
}

// ---------------- step controller (verbatim R13) ----------------
__global__ void update_kernel() {
  __shared__ float red[256];
  int tid = threadIdx.x;
  float s0 = 0.f;
  for (int i = tid; i < 2048; i += 256) s0 += g_partial[i];
  red[tid] = s0;
  __syncthreads();
  for (int s = 128; s > 0; s >>= 1) { if (tid < s) red[tid] += red[tid+s]; __syncthreads(); }
  if (tid == 0) {
    float err_norm = sqrtf(red[0] * (1.f / (float)NSTATE));
    float tcur = g_t, dt = g_dt;
    float dtc  = fminf(dt, 1.f - tcur);
    bool done = tcur >= 1.f - 1e-7f;
    bool adv  = (err_norm <= 1.f) && (!done);
    g_accept = adv ? 1 : 0;
    g_t = adv ? (tcur + dtc) : tcur;
    float safe = fmaxf(err_norm, 1e-10f);
    float factor = 0.9f * powf(safe, -0.2f);
    factor = fminf(fmaxf(factor, 0.2f), 10.f);
    g_dt = done ? dt : dtc * factor;
  }
}

__global__ void commit_kernel() {
  if (g_accept == 0) return;
  int i = blockIdx.x * 256 + threadIdx.x;
  g_y[i] = g_y5[i];
}

// ---------------- final linear head (verbatim R13) ----------------
__global__ __launch_bounds__(256) void head_kernel(const float* __restrict__ wl,
                                                   const float* __restrict__ bl,
                                                   float* __restrict__ out) {
  __shared__ float ys[8192];
  __shared__ float red[256];
  int b = blockIdx.x, tid = threadIdx.x;
  const float* yb = g_y + (size_t)b * 8192;
  for (int i = tid; i < 8192; i += 256) {
    int px = i >> 3, c = i & 7;
    ys[c*1024 + px] = yb[i];
  }
  __syncthreads();
  for (int o = 0; o < 10; o++) {
    float s = 0.f;
    const float* wo = wl + (size_t)o * 8192;
    for (int i = tid; i < 8192; i += 256) s += wo[i] * ys[i];
    red[tid] = s; __syncthreads();
    for (int st = 128; st > 0; st >>= 1) { if (tid < st) red[tid] += red[tid+st]; __syncthreads(); }
    if (tid == 0) out[b*10 + o] = red[0] + bl[o];
    __syncthreads();
  }
}

// ---------------- launcher ----------------
extern "C" void kernel_launch(void* const* d_in, const int* in_sizes, int n_in,
                              void* d_out, int out_size) {
  const float* x  = (const float*)d_in[0];
  const float* w1 = (const float*)d_in[1];
  const float* b1 = (const float*)d_in[2];
  const float* w2 = (const float*)d_in[3];
  const float* b2 = (const float*)d_in[4];
  const float* w3 = (const float*)d_in[5];
  const float* b3 = (const float*)d_in[6];
  const float* wl = (const float*)d_in[7];
  const float* bl = (const float*)d_in[8];
  float* out = (float*)d_out;

  cudaFuncSetAttribute(fused_kernel, cudaFuncAttributeMaxDynamicSharedMemorySize, SMEM_BYTES);

  init_kernel<<<NSTATE/256, 256>>>(x);
  prep_kernel<<<72, 256>>>(w1, b1, w2, b2, w3, b3);
  for (int step = 0; step < N_STEPS; step++) {
    commit_kernel<<<NSTATE/256, 256>>>();
    for (int s = 0; s < 7; s++)
      fused_kernel<<<dim3(B_IMG, 8), 384, SMEM_BYTES>>>(s);
    err_kernel<<<NSTATE/256, 256>>>();
    update_kernel<<<1, 256>>>();
  }
  commit_kernel<<<NSTATE/256, 256>>>();
  head_kernel<<<B_IMG, 256>>>(wl, bl, out);
}

// round 15
// speedup vs baseline: 1.7585x; 1.7585x over previous
#include <cuda_runtime.h>
#include <cuda_fp16.h>
#include <math.h>

#define B_IMG   64
#define NPIX    1024
#define NSTATE  (B_IMG*8*NPIX)      // 524288
#define N_STEPS 24

typedef unsigned long long ull;
typedef unsigned int uint;

__device__ __forceinline__ ull pack2(float lo, float hi) {
  ull r; asm("mov.b64 %0, {%1, %2};" : "=l"(r) : "f"(lo), "f"(hi)); return r;
}
__device__ __forceinline__ float2 unpk(ull v) {
  float2 f; asm("mov.b64 {%0, %1}, %2;" : "=f"(f.x), "=f"(f.y) : "l"(v)); return f;
}
#define FMA2(d,a,b) asm("fma.rn.f32x2 %0, %1, %2, %0;" : "+l"(d) : "l"(a), "l"(b))

// fp16 m16n8k16 mma, fp32 accum
__device__ __forceinline__ void mma_f16(float* d, const uint* a, uint b0, uint b1) {
  asm volatile("mma.sync.aligned.m16n8k16.row.col.f32.f16.f16.f32 "
    "{%0,%1,%2,%3}, {%4,%5,%6,%7}, {%8,%9}, {%0,%1,%2,%3};"
    : "+f"(d[0]), "+f"(d[1]), "+f"(d[2]), "+f"(d[3])
    : "r"(a[0]), "r"(a[1]), "r"(a[2]), "r"(a[3]), "r"(b0), "r"(b1));
}
__device__ __forceinline__ void cpa16(void* smem_dst, const void* gsrc) {
  unsigned s = (unsigned)__cvta_generic_to_shared(smem_dst);
  asm volatile("cp.async.ca.shared.global [%0], [%1], 16;" :: "r"(s), "l"(gsrc));
}
#define CP_COMMIT() asm volatile("cp.async.commit_group;")
#define CP_WAIT0()  asm volatile("cp.async.wait_group 0;")

// split fp32 -> (fp16 hi, fp16 residual) packed low|high
__device__ __forceinline__ uint h2split(float f) {
  __half h0 = __float2half_rn(f);
  float r = f - __half2float(h0);
  __half h1 = __float2half_rn(r);
  return (uint)__half_as_ushort(h0) | ((uint)__half_as_ushort(h1) << 16);
}
__device__ __forceinline__ uint hdup(__half h) {
  uint u = (uint)__half_as_ushort(h);
  return u | (u << 16);
}

// ---------------- device state ----------------
__device__ float g_y[NSTATE];
__device__ float g_y5[NSTATE];
__device__ float g_k[7][NSTATE];
__device__ float g_t, g_dt;
__device__ float g_partial[2048];
__device__ int   g_accept;

// packed weights
__device__ uint4 g_w2h[9216];   // [cc8][t9][mt4][g8][tq4]: A-frag uint4 (fp16 pairs)
__device__ ull g_w1s[256];      // [c8][o2_32]
__device__ ull g_w1t[32], g_b1p[32];
__device__ ull g_w3s[256];      // [ci64][o2_4]
__device__ ull g_w3t[4], g_b3p[4];
__device__ float g_w0f[576];    // conv2 t-channel [och64][tap9]
__device__ float g_b2f[64];

__constant__ float c_toff[7] = {0.f, 0.2f, 0.3f, 0.8f, (float)(8.0/9.0), 1.f, 1.f};
__constant__ float c_coef[7][6] = {
  {0,0,0,0,0,0},
  {0.2f,0,0,0,0,0},
  {(float)(3.0/40.0),(float)(9.0/40.0),0,0,0,0},
  {(float)(44.0/45.0),(float)(-56.0/15.0),(float)(32.0/9.0),0,0,0},
  {(float)(19372.0/6561.0),(float)(-25360.0/2187.0),(float)(64448.0/6561.0),(float)(-212.0/729.0),0,0},
  {(float)(9017.0/3168.0),(float)(-355.0/33.0),(float)(46732.0/5247.0),(float)(49.0/176.0),(float)(-5103.0/18656.0),0},
  {(float)(35.0/384.0),0.f,(float)(500.0/1113.0),(float)(125.0/192.0),(float)(-2187.0/6784.0),(float)(11.0/84.0)}
};
#define B1f ((float)(35.0/384.0))
#define B3f ((float)(500.0/1113.0))
#define B4f ((float)(125.0/192.0))
#define B5f ((float)(-2187.0/6784.0))
#define B6f ((float)(11.0/84.0))
#define E1f ((float)(71.0/57600.0))
#define E3f ((float)(-71.0/16695.0))
#define E4f ((float)(71.0/1920.0))
#define E5f ((float)(-17253.0/339200.0))
#define E6f ((float)(22.0/525.0))
#define E7f ((float)(-1.0/40.0))

// ---------------- init ----------------
__global__ void init_kernel(const float* __restrict__ x) {
  int i = blockIdx.x * 256 + threadIdx.x;
  if (i == 0) { g_t = 0.f; g_dt = 0.1f; g_accept = 0; }
  if (i < NSTATE) {
    int c = i & 7, p = (i >> 3) & 1023, b = i >> 13;
    g_y[i] = (c < 3) ? x[b*3*NPIX + c*NPIX + p] : 0.f;
  }
}

// ---------------- weight prep ----------------
__global__ void prep_kernel(const float* __restrict__ w1, const float* __restrict__ b1,
                            const float* __restrict__ w2, const float* __restrict__ b2,
                            const float* __restrict__ w3, const float* __restrict__ b3) {
  int i = blockIdx.x * 256 + threadIdx.x;
  if (i < 9216) {
    int tq = i & 3;
    int g  = (i >> 2) & 7;
    int mt = (i >> 5) & 3;
    int t  = (i >> 7) % 9;
    int cc = i / 1152;
    int och0 = mt*16 + g;
    uint4 u;
    u.x = h2split(w2[(och0  )*585 + (cc*8 + tq + 1)*9 + t]);
    u.y = h2split(w2[(och0+8)*585 + (cc*8 + tq + 1)*9 + t]);
    u.z = h2split(w2[(och0  )*585 + (cc*8 + tq + 5)*9 + t]);
    u.w = h2split(w2[(och0+8)*585 + (cc*8 + tq + 5)*9 + t]);
    g_w2h[i] = u;
  }
  if (i < 256) {
    int c = i >> 5, o2 = i & 31;
    g_w1s[i] = pack2(w1[(2*o2)*9 + 1 + c], w1[(2*o2+1)*9 + 1 + c]);
  }
  if (i < 32) {
    g_w1t[i] = pack2(w1[(2*i)*9], w1[(2*i+1)*9]);
    g_b1p[i] = pack2(b1[2*i], b1[2*i+1]);
  }
  if (i < 256) {
    int c = i >> 2, o2 = i & 3;
    g_w3s[i] = pack2(w3[(2*o2)*65 + 1 + c], w3[(2*o2+1)*65 + 1 + c]);
  }
  if (i < 4) {
    g_w3t[i] = pack2(w3[(2*i)*65], w3[(2*i+1)*65]);
    g_b3p[i] = pack2(b3[2*i], b3[2*i+1]);
  }
  if (i < 576) {
    int och = i / 9, t = i % 9;
    g_w0f[i] = w2[och*585 + t];
  }
  if (i < 64) g_b2f[i] = b2[i];
}

// ---------------- fused stage kernel: warp-specialized fp16x4 ----------------
// grid (64 img, 8 tiles); block 384 thr = 12 warps.
// Warps 0-7 = CONSUMERS: warp w -> row-group cw = w>>1, och-half oh = w&1.
// Warps 8-11 = PRODUCERS (conv1 + weight cp.async).
// conv2 via 2x m16n8k16.f16 mma per (tap, m-tile, n-tile): terms a0b0+a1b0, a0b1+a1b1.
#define HP 210            // h1q pitch (uint4)
#define HB 840            // h1q buffer stride (uint4) = 4*HP
#define SM_YTS   0        // float yts[204][8]                 6528 B
#define SM_H1    6528     // uint4 h1q[2][4][HP]              26880 B
#define SM_WB    33408    // uint4 wb[2][1152]                36864 B  (h2s overlays)
#define SM_W1    70272    // ull w1s[256]                      2048 B
#define SM_B1    72320    // ull bias1[32]                      256 B
#define SM_W3    72576    // ull w3s[256]                      2048 B
#define SM_W0    74624    // float w0f[576]                    2304 B
#define SM_B2    76928    // float b2f[64]                      256 B
#define SMEM_BYTES 77184

__global__ __launch_bounds__(384, 2) void fused_kernel(int stage) {
  extern __shared__ char smraw[];
  float* yts  = (float*)(smraw + SM_YTS);
  uint4* h1q  = (uint4*)(smraw + SM_H1);
  uint4* wbu  = (uint4*)(smraw + SM_WB);
  float* h2s  = (float*)(smraw + SM_WB);       // overlay after K loop
  ull*   w1s  = (ull*)  (smraw + SM_W1);
  ull*   bias1= (ull*)  (smraw + SM_B1);
  ull*   w3s  = (ull*)  (smraw + SM_W3);
  float* w0f  = (float*)(smraw + SM_W0);
  float* b2f  = (float*)(smraw + SM_B2);

  int tid  = threadIdx.x;
  int b    = blockIdx.x;
  int tile = blockIdx.y;
  int r0   = tile * 4;

  int warp = tid >> 5, lane = tid & 31;
  int g   = lane >> 2;
  int cq  = lane & 3;
  bool is_cons = (warp < 8);
  int cw   = warp >> 1;     // consumer row group (0..3)
  int oh   = warp & 1;      // consumer och half (0..1)
  int ptid = tid - 256;     // producer thread id (0..127)

  float tcur = g_t;
  float dtc  = fminf(g_dt, 1.f - tcur);
  float teval = tcur + c_toff[stage] * dtc;
  ull tev2 = pack2(teval, teval);

  // small weights -> smem (all threads)
  for (int i = tid; i < 256; i += 384) w1s[i] = g_w1s[i];
  for (int i = tid; i < 256; i += 384) w3s[i] = g_w3s[i];
  for (int i = tid; i < 576; i += 384) w0f[i] = g_w0f[i];
  if (tid < 64) b2f[tid] = g_b2f[tid];
  if (tid < 32) { ull bb = g_b1p[tid]; FMA2(bb, tev2, g_w1t[tid]); bias1[tid] = bb; }

  // ---- phase A: stage-combined state into yts (haloed 6x34) — verbatim float code ----
  for (int p = tid; p < 204; p += 384) {
    int prow = p / 34, pcol = p - prow*34;
    int gr = r0 - 1 + prow, gc = pcol - 1;
    float4 o0 = make_float4(0.f,0.f,0.f,0.f), o1 = o0;
    if (gr >= 0 && gr < 32 && gc >= 0 && gc < 32) {
      int idx = b*1024 + gr*32 + gc;
      const float4* yp = (const float4*)g_y;
      o0 = yp[idx*2]; o1 = yp[idx*2+1];
      for (int j = 0; j < stage; j++) {
        float cf = c_coef[stage][j];
        if (cf != 0.f) {
          float a = dtc * cf;
          const float4* kj = (const float4*)g_k[j];
          float4 k0 = kj[idx*2], k1 = kj[idx*2+1];
          o0.x+=a*k0.x; o0.y+=a*k0.y; o0.z+=a*k0.z; o0.w+=a*k0.w;
          o1.x+=a*k1.x; o1.y+=a*k1.y; o1.z+=a*k1.z; o1.w+=a*k1.w;
        }
      }
    }
    float4* dst = (float4*)(yts + p*8);
    dst[0] = o0; dst[1] = o1;
  }
  __syncthreads();   // yts ready for producers

  // consumer accumulators: acc[mtl2][nt4][4]
  float acc[2][4][4];
  #pragma unroll
  for (int mtl = 0; mtl < 2; mtl++)
    #pragma unroll
    for (int nt = 0; nt < 4; nt++)
      #pragma unroll
      for (int q = 0; q < 4; q++) acc[mtl][nt][q] = 0.f;

  const int abase = g*4 + cq;               // A: + t*128 + (oh*2+mtl)*32
  const int hbase = cq*HP + cw*34 + g;      // B: + kh*34 + kw + nt*8 (+ buf*HB)

  // ---- 9 phases: producers(chunk ph) || consumers(chunk ph-1) ----
  #pragma unroll 1
  for (int ph = 0; ph < 9; ph++) {
    if (!is_cons) {
      // PRODUCERS: weight copy chunk ph, conv1 chunk ph (float code verbatim),
      // then fp16 split/pack.
      if (ph < 8) {
        const int cc = ph;
        const int buf = cc & 1;
        {
          const uint4* src = g_w2h + cc*1152;
          uint4* dst = wbu + buf*1152;
          for (int i = ptid; i < 1152; i += 128) cpa16(dst + i, src + i);
          CP_COMMIT();
        }
        #pragma unroll 1
        for (int p = ptid; p < 204; p += 128) {
          int prow = p / 34, pcol = p - prow*34;
          int gr = r0 - 1 + prow, gc = pcol - 1;
          float o[8];
          if (gr >= 0 && gr < 32 && gc >= 0 && gc < 32) {
            const float4* yv = (const float4*)(yts + p*8);
            float4 a4 = yv[0], b4 = yv[1];
            float yf[8] = {a4.x, a4.y, a4.z, a4.w, b4.x, b4.y, b4.z, b4.w};
            ull yy[8];
            #pragma unroll
            for (int c8 = 0; c8 < 8; c8++) yy[c8] = pack2(yf[c8], yf[c8]);
            #pragma unroll
            for (int q = 0; q < 4; q++) {
              ull aq = bias1[cc*4 + q];
              #pragma unroll
              for (int c8 = 0; c8 < 8; c8++) FMA2(aq, yy[c8], w1s[c8*32 + cc*4 + q]);
              float2 f = unpk(aq);
              o[2*q]   = fmaxf(f.x, 0.f);
              o[2*q+1] = fmaxf(f.y, 0.f);
            }
          } else {
            #pragma unroll
            for (int q = 0; q < 8; q++) o[q] = 0.f;
          }
          // fp16 split + dup-pack: uint4 = (dup b0[ci], dup b0[ci+4], dup b1[ci], dup b1[ci+4])
          #pragma unroll
          for (int ci = 0; ci < 4; ci++) {
            float v0 = o[ci], v1 = o[ci+4];
            __half p00 = __float2half_rn(v0);
            __half p01 = __float2half_rn(v0 - __half2float(p00));
            __half p10 = __float2half_rn(v1);
            __half p11 = __float2half_rn(v1 - __half2float(p10));
            h1q[buf*HB + ci*HP + p] = make_uint4(hdup(p00), hdup(p10), hdup(p01), hdup(p11));
          }
        }
        CP_WAIT0();
      }
    } else {
      // CONSUMERS: mma chunk ph-1, och-half oh
      if (ph >= 1) {
        const int cc = ph - 1;
        const int buf = cc & 1;
        const uint4* wc = wbu + buf*1152;
        #pragma unroll
        for (int t = 0; t < 9; t++) {
          const int kh = t / 3, kw = t - kh*3;
          uint4 Bv[4];
          #pragma unroll
          for (int nt = 0; nt < 4; nt++)
            Bv[nt] = h1q[buf*HB + hbase + kh*34 + kw + nt*8];
          #pragma unroll
          for (int mtl = 0; mtl < 2; mtl++) {
            uint4 A = wc[abase + t*128 + (oh*2 + mtl)*32];
            uint aA[4] = {A.x, A.y, A.z, A.w};
            #pragma unroll
            for (int nt = 0; nt < 4; nt++) {
              mma_f16(acc[mtl][nt], aA, Bv[nt].x, Bv[nt].y);   // (a0+a1)*b0
              mma_f16(acc[mtl][nt], aA, Bv[nt].z, Bv[nt].w);   // (a0+a1)*b1
            }
          }
        }
      }
    }
    __syncthreads();
  }

  // ---- epilogue (consumers): t-channel + bias + relu -> h2s[row4][och64][33] ----
  // Float expressions verbatim R14.
  if (is_cons) {
    int gr = r0 + cw;
    bool r0ok = (gr != 0);
    bool r2ok = (gr != 31);
    #pragma unroll
    for (int mtl = 0; mtl < 2; mtl++) {
      #pragma unroll
      for (int rh = 0; rh < 2; rh++) {
        int och = (oh*2 + mtl)*16 + g + rh*8;
        const float* w0 = w0f + och*9;
        float cs0 = w0[3], cs1 = w0[4], cs2 = w0[5];
        if (r0ok) { cs0 += w0[0]; cs1 += w0[1]; cs2 += w0[2]; }
        if (r2ok) { cs0 += w0[6]; cs1 += w0[7]; cs2 += w0[8]; }
        float ball = cs0 + cs1 + cs2;
        float bias = b2f[och];
        float* hrow = h2s + (cw*64 + och)*33;
        #pragma unroll
        for (int nt = 0; nt < 4; nt++) {
          #pragma unroll
          for (int cb = 0; cb < 2; cb++) {
            int colx = nt*8 + 2*cq + cb;
            float s = ball;
            if (colx == 0)  s -= cs0;
            if (colx == 31) s -= cs2;
            float v = acc[mtl][nt][rh*2 + cb] + teval*s + bias;
            hrow[colx] = fmaxf(v, 0.f);
          }
        }
      }
    }
  }
  __syncthreads();

  // ---- conv3 (65->8 1x1): 256 of 384 threads, 2 threads/px — verbatim R14 ----
  if (tid < 256) {
    int px   = tid >> 1;
    int half = tid & 1;
    int row = px >> 5, col = px & 31;
    int o2a = half*2, o2b = half*2 + 1;
    ull k0 = g_b3p[o2a]; FMA2(k0, tev2, g_w3t[o2a]);
    ull k1 = g_b3p[o2b]; FMA2(k1, tev2, g_w3t[o2b]);
    const float* hcol = h2s + (row*64)*33 + col;
    #pragma unroll 8
    for (int c = 0; c < 64; c++) {
      float h = hcol[c*33];
      ull hh = pack2(h, h);
      FMA2(k0, hh, w3s[c*4 + o2a]);
      FMA2(k1, hh, w3s[c*4 + o2b]);
    }
    float2 f0 = unpk(k0), f1 = unpk(k1);
    int idx = b*1024 + (r0 + row)*32 + col;
    ((float4*)g_k[stage])[idx*2 + half] = make_float4(f0.x, f0.y, f1.x, f1.y);
  }
}

// ---------------- y5 + error partials (verbatim R14) ----------------
__global__ __launch_bounds__(256) void err_kernel() {
  __shared__ float red[256];
  int tid = threadIdx.x;
  int e = blockIdx.x * 256 + tid;
  float dtc = fminf(g_dt, 1.f - g_t);
  float k0 = g_k[0][e], k2 = g_k[2][e], k3 = g_k[3][e];
  float k4 = g_k[4][e], k5 = g_k[5][e], k6 = g_k[6][e];
  float yv = g_y[e];
  float y5 = yv + dtc*(B1f*k0 + B3f*k2 + B4f*k3 + B5f*k4 + B6f*k5);
  g_y5[e] = y5;
  float err = dtc*(E1f*k0 + E3f*k2 + E4f*k3 + E5f*k4 + E6f*k5 + E7f*k6);
  float tol = 1e-3f + 1e-3f * fmaxf(fabsf(yv), fabsf(y5));
  float r = err / tol;
  red[tid] = r * r;
  __syncthreads();
  for (int s = 128; s > 0; s >>= 1) { if (tid < s) red[tid] += red[tid+s]; __syncthreads(); }
  if (tid == 0) g_partial[blockIdx.x] = red[0];
}

// ---------------- step controller (verbatim R14) ----------------
__global__ void update_kernel() {
  __shared__ float red[256];
  int tid = threadIdx.x;
  float s0 = 0.f;
  for (int i = tid; i < 2048; i += 256) s0 += g_partial[i];
  red[tid] = s0;
  __syncthreads();
  for (int s = 128; s > 0; s >>= 1) { if (tid < s) red[tid] += red[tid+s]; __syncthreads(); }
  if (tid == 0) {
    float err_norm = sqrtf(red[0] * (1.f / (float)NSTATE));
    float tcur = g_t, dt = g_dt;
    float dtc  = fminf(dt, 1.f - tcur);
    bool done = tcur >= 1.f - 1e-7f;
    bool adv  = (err_norm <= 1.f) && (!done);
    g_accept = adv ? 1 : 0;
    g_t = adv ? (tcur + dtc) : tcur;
    float safe = fmaxf(err_norm, 1e-10f);
    float factor = 0.9f * powf(safe, -0.2f);
    factor = fminf(fmaxf(factor, 0.2f), 10.f);
    g_dt = done ? dt : dtc * factor;
  }
}

__global__ void commit_kernel() {
  if (g_accept == 0) return;
  int i = blockIdx.x * 256 + threadIdx.x;
  g_y[i] = g_y5[i];
}

// ---------------- final linear head (verbatim R14) ----------------
__global__ __launch_bounds__(256) void head_kernel(const float* __restrict__ wl,
                                                   const float* __restrict__ bl,
                                                   float* __restrict__ out) {
  __shared__ float ys[8192];
  __shared__ float red[256];
  int b = blockIdx.x, tid = threadIdx.x;
  const float* yb = g_y + (size_t)b * 8192;
  for (int i = tid; i < 8192; i += 256) {
    int px = i >> 3, c = i & 7;
    ys[c*1024 + px] = yb[i];
  }
  __syncthreads();
  for (int o = 0; o < 10; o++) {
    float s = 0.f;
    const float* wo = wl + (size_t)o * 8192;
    for (int i = tid; i < 8192; i += 256) s += wo[i] * ys[i];
    red[tid] = s; __syncthreads();
    for (int st = 128; st > 0; st >>= 1) { if (tid < st) red[tid] += red[tid+st]; __syncthreads(); }
    if (tid == 0) out[b*10 + o] = red[0] + bl[o];
    __syncthreads();
  }
}

// ---------------- launcher ----------------
extern "C" void kernel_launch(void* const* d_in, const int* in_sizes, int n_in,
                              void* d_out, int out_size) {
  const float* x  = (const float*)d_in[0];
  const float* w1 = (const float*)d_in[1];
  const float* b1 = (const float*)d_in[2];
  const float* w2 = (const float*)d_in[3];
  const float* b2 = (const float*)d_in[4];
  const float* w3 = (const float*)d_in[5];
  const float* b3 = (const float*)d_in[6];
  const float* wl = (const float*)d_in[7];
  const float* bl = (const float*)d_in[8];
  float* out = (float*)d_out;

  cudaFuncSetAttribute(fused_kernel, cudaFuncAttributeMaxDynamicSharedMemorySize, SMEM_BYTES);

  init_kernel<<<NSTATE/256, 256>>>(x);
  prep_kernel<<<72, 256>>>(w1, b1, w2, b2, w3, b3);
  for (int step = 0; step < N_STEPS; step++) {
    commit_kernel<<<NSTATE/256, 256>>>();
    for (int s = 0; s < 7; s++)
      fused_kernel<<<dim3(B_IMG, 8), 384, SMEM_BYTES>>>(s);
    err_kernel<<<NSTATE/256, 256>>>();
    update_kernel<<<1, 256>>>();
  }
  commit_kernel<<<NSTATE/256, 256>>>();
  head_kernel<<<B_IMG, 256>>>(wl, bl, out);
}